// round 16
// baseline (speedup 1.0000x reference)
#include <cuda_runtime.h>
#include <cstdint>

// Problem constants
#define NUM_VERTS 6890
#define NUM_FACES 13776
#define IMG_H 1024
#define IMG_W 1024
#define NBATCH 16
#define HW (IMG_H * IMG_W)
#define PLANE_FLOATS (HW * 3)            // 3,145,728 floats per batch plane
#define THREADS 256
#define TILE_PX 1024                     // pixels per tile
#define TILE_FLOATS (TILE_PX * 3)        // 3072 floats = 12KB per buffer
#define TILE_BYTES (TILE_FLOATS * 4)     // 12288
#define TILES_PER_CTA 2
#define NBUF 2

// Precomputed per-face vertex attributes, 64B-aligned rows:
// row f = { v0.xyz _, v1.xyz _, v2.xyz _, pad }. 882KB -> L2-resident.
__device__ __align__(64) float4 g_face_attr[NUM_FACES][4];

// Kernel A: build the face-attr table (batch-0 vertices only; the reference's
// pixel gather never applies a per-batch face offset and batch-0 vertex
// offset is 0, so only batch 0 matters).
__global__ void __launch_bounds__(256) build_face_attr(
    const float* __restrict__ verts,   // (N, V, 3) f32
    const int*   __restrict__ faces)   // (F, 3) i32
{
    const int f = blockIdx.x * blockDim.x + threadIdx.x;
    if (f >= NUM_FACES) return;
    const int i0 = faces[f * 3 + 0];
    const int i1 = faces[f * 3 + 1];
    const int i2 = faces[f * 3 + 2];
    const float* v0 = verts + (size_t)i0 * 3;
    const float* v1 = verts + (size_t)i1 * 3;
    const float* v2 = verts + (size_t)i2 * 3;
    g_face_attr[f][0] = make_float4(v0[0], v0[1], v0[2], 0.0f);
    g_face_attr[f][1] = make_float4(v1[0], v1[1], v1[2], 0.0f);
    g_face_attr[f][2] = make_float4(v2[0], v2[1], v2[2], 0.0f);
}

// Kernel B: each CTA computes 2 tiles of 1024 px into alternating 12KB smem
// buffers; the 16-way batch broadcast of tile t drains via async TMA bulk
// copies WHILE tile t+1 is being computed. Store traffic never touches the
// LSU/L1tex path, which is left entirely to the random face gathers.
__global__ void __launch_bounds__(THREADS) render_kernel(
    const int*   __restrict__ pix,     // (H*W) i32
    const float* __restrict__ bary,    // (H*W, 3) f32
    float* __restrict__ out)           // (16, H, W, 3) f32
{
    __shared__ __align__(128) float seg[NBUF][TILE_FLOATS];

    const int tid = threadIdx.x;

    #pragma unroll
    for (int t = 0; t < TILES_PER_CTA; t++) {
        const int tile = blockIdx.x * TILES_PER_CTA + t;
        const int p0   = tile * TILE_PX + tid * 4;          // 4 px/thread
        float* buf = seg[t & (NBUF - 1)];

        // ---- pix first (heads the gather chain), then bary ----
        const int4 px = *reinterpret_cast<const int4*>(pix + p0);
        const float4* b4 = reinterpret_cast<const float4*>(bary + (size_t)p0 * 3);
        const float4 bA = b4[0];
        const float4 bB = b4[1];
        const float4 bC = b4[2];

        const int pf[4] = { px.x, px.y, px.z, px.w };
        const float bw[4][3] = {
            { bA.x, bA.y, bA.z },
            { bA.w, bB.x, bB.y },
            { bB.z, bB.w, bC.x },
            { bC.y, bC.z, bC.w }
        };

        // ---- Compute 4 pixels into this tile's smem buffer ----
        float* sp = buf + tid * 12;
        #pragma unroll
        for (int i = 0; i < 4; i++) {
            float r0 = 0.0f, r1 = 0.0f, r2 = 0.0f;
            const int f = pf[i];
            if (f >= 0) {
                // 3 x LDG.128 from one 64B row; table is L2-resident.
                const float4 v0 = __ldg(&g_face_attr[f][0]);
                const float4 v1 = __ldg(&g_face_attr[f][1]);
                const float4 v2 = __ldg(&g_face_attr[f][2]);
                const float w0 = bw[i][0], w1 = bw[i][1], w2 = bw[i][2];
                r0 = fmaf(w2, v2.x, fmaf(w1, v1.x, w0 * v0.x));
                r1 = fmaf(w2, v2.y, fmaf(w1, v1.y, w0 * v0.y));
                r2 = fmaf(w2, v2.z, fmaf(w1, v1.z, w0 * v0.z));
            }
            sp[i * 3 + 0] = r0;
            sp[i * 3 + 1] = r1;
            sp[i * 3 + 2] = r2;
        }
        __syncthreads();

        // ---- Async TMA bulk broadcast: 16 x 12KB copies, non-blocking ----
        if (tid == 0) {
            asm volatile("fence.proxy.async.shared::cta;" ::: "memory");
            uint32_t s_addr;
            asm("{ .reg .u64 u; cvta.to.shared.u64 u, %1; cvt.u32.u64 %0, u; }"
                : "=r"(s_addr) : "l"(buf));
            const size_t seg_off = (size_t)tile * TILE_FLOATS;
            #pragma unroll
            for (int b = 0; b < NBATCH; b++) {
                float* dst = out + (size_t)b * PLANE_FLOATS + seg_off;
                asm volatile(
                    "cp.async.bulk.global.shared::cta.bulk_group [%0], [%1], %2;"
                    :: "l"(dst), "r"(s_addr), "n"((int)TILE_BYTES) : "memory");
            }
            asm volatile("cp.async.bulk.commit_group;" ::: "memory");
        }
        // No wait here: next iteration writes the OTHER buffer, so tile t's
        // copies drain concurrently with tile t+1's gathers.
        __syncthreads();
    }

    // Final drain: keep the CTA (and its smem) alive until all bulk-group
    // reads have completed. Only the issuing thread must wait.
    if (tid == 0) {
        asm volatile("cp.async.bulk.wait_group.read 0;" ::: "memory");
    }
}

extern "C" void kernel_launch(void* const* d_in, const int* in_sizes, int n_in,
                              void* d_out, int out_size)
{
    // metadata order: verts_attr (f32), face_tensor (i32), pix_to_face (i32), bary_coords (f32)
    const float* verts = (const float*)d_in[0];
    const int*   faces = (const int*)d_in[1];
    const int*   pix   = (const int*)d_in[2];
    const float* bary  = (const float*)d_in[3];
    float* out = (float*)d_out;

    build_face_attr<<<(NUM_FACES + 255) / 256, 256>>>(verts, faces);
    const int nblocks = HW / (TILE_PX * TILES_PER_CTA);   // 512
    render_kernel<<<nblocks, THREADS>>>(pix, bary, out);
}